// round 9
// baseline (speedup 1.0000x reference)
#include <cuda_runtime.h>
#include <cstdint>

// out[0:100]   = dot(I[row,:], p), row = inds1[m,0]*28 + inds1[m,1]
// out[100:200] = dot(J[row,:], p), P = 50000.
//
// v8: async-proxy streaming. Each block handles 4 rows x 1/5 of the K dim.
// cp.async.bulk (UBLKCP) copies 5 streams (4 rows + p) into double-buffered
// SMEM stages; compute reads SMEM only. Fused last-block reduction.

#define P_DIM     50000
#define P_VEC4    12500
#define SPLIT     5
#define CHUNK4    2500            // float4 per stream per block (12500/5, exact)
#define STAGE4    512             // float4 per stream per stage
#define NSTAGES   5               // 4*512 + 452
#define CARD2     100
#define NOUT      200
#define RPB       4
#define NBLOCKS   250             // 50 groups * SPLIT  (<= 296 conc @ occ 2)
#define W_IMG     28
#define NTHREADS  512
#define NWARPS    16
#define NSTREAMS  (RPB + 1)
#define STAGE_BYTES (STAGE4 * 16)               // 8192 B per stream
#define BUF_BYTES   (NSTREAMS * STAGE_BYTES)    // 40960 B per stage
#define SMEM_DYN    (2 * BUF_BYTES)             // 81920 B

__device__ float        g_partials[NOUT * SPLIT];
__device__ unsigned int g_ticket = 0;

__device__ __forceinline__ uint32_t smem_u32(const void* p) {
    uint32_t a;
    asm("{ .reg .u64 t; cvta.to.shared.u64 t, %1; cvt.u32.u64 %0, t; }"
        : "=r"(a) : "l"(p));
    return a;
}

__device__ __forceinline__ void mbar_init(uint32_t bar, uint32_t cnt) {
    asm volatile("mbarrier.init.shared.b64 [%0], %1;" :: "r"(bar), "r"(cnt) : "memory");
}
__device__ __forceinline__ void mbar_expect_tx(uint32_t bar, uint32_t bytes) {
    asm volatile("mbarrier.arrive.expect_tx.shared.b64 _, [%0], %1;"
                 :: "r"(bar), "r"(bytes) : "memory");
}
__device__ __forceinline__ void mbar_wait(uint32_t bar, uint32_t parity) {
    uint32_t done;
    asm volatile(
        "{ .reg .pred p;\n"
        "  mbarrier.try_wait.parity.acquire.cta.shared::cta.b64 p, [%1], %2;\n"
        "  selp.b32 %0, 1, 0, p; }"
        : "=r"(done) : "r"(bar), "r"(parity) : "memory");
    if (!done) {
        asm volatile(
            "{ .reg .pred P1;\n"
            "WAIT_%=:\n"
            "  mbarrier.try_wait.parity.acquire.cta.shared::cta.b64 P1, [%0], %1, 0x989680;\n"
            "  @P1 bra.uni DONE_%=;\n"
            "  bra.uni WAIT_%=;\n"
            "DONE_%=: }"
            :: "r"(bar), "r"(parity) : "memory");
    }
}
__device__ __forceinline__ void bulk_g2s(uint32_t dst, const void* src,
                                         uint32_t bytes, uint32_t bar) {
    asm volatile(
        "cp.async.bulk.shared::cta.global.mbarrier::complete_tx::bytes "
        "[%0], [%1], %2, [%3];"
        :: "r"(dst), "l"(src), "r"(bytes), "r"(bar) : "memory");
}

__global__ __launch_bounds__(NTHREADS)
void gather_dot_v8(const float* __restrict__ p,
                   const float* __restrict__ I,
                   const float* __restrict__ J,
                   const int*   __restrict__ inds1,
                   const int*   __restrict__ inds2,
                   float*       __restrict__ out)
{
    extern __shared__ __align__(128) unsigned char smem[];
    __shared__ __align__(8) uint64_t mbar_storage[2];
    __shared__ float ws[RPB][NWARPS];
    __shared__ bool  s_last;

    const int tid   = threadIdx.x;
    const int group = blockIdx.x / SPLIT;   // 0..49
    const int chunk = blockIdx.x % SPLIT;   // 0..4
    const int mbase = group * RPB;          // never straddles the I/J boundary

    const float* mat;
    const int*   ind;
    if (mbase < CARD2) { mat = I; ind = inds1 + 2 * mbase; }
    else               { mat = J; ind = inds2 + 2 * (mbase - CARD2); }

    const uint32_t sbase = smem_u32(smem);
    const uint32_t bar0  = smem_u32(&mbar_storage[0]);
    const uint32_t bar1  = smem_u32(&mbar_storage[1]);

    if (tid == 0) { mbar_init(bar0, 1); mbar_init(bar1, 1); }
    __syncthreads();

    // Global source base pointers (byte addresses), offset to this chunk.
    const char* src[NSTREAMS];
    #pragma unroll
    for (int k = 0; k < RPB; k++) {
        int row = ind[2 * k] * W_IMG + ind[2 * k + 1];
        src[k] = (const char*)(mat + (size_t)row * P_DIM) + (size_t)chunk * CHUNK4 * 16;
    }
    src[RPB] = (const char*)p + (size_t)chunk * CHUNK4 * 16;

    // Producer: one thread, double-buffered bulk copies.
    // Stage s -> buffer s&1, barrier s&1. Buffer reuse is safe because the
    // __syncthreads() at the end of compute iteration s-1 precedes issue(s+1).
    auto issue = [&](int s) {
        const int     len   = (s == NSTAGES - 1) ? (CHUNK4 - (NSTAGES - 1) * STAGE4) : STAGE4;
        const uint32_t bytes = (uint32_t)len * 16u;
        const uint32_t bar   = (s & 1) ? bar1 : bar0;
        const uint32_t dst0  = sbase + (uint32_t)(s & 1) * BUF_BYTES;
        mbar_expect_tx(bar, bytes * NSTREAMS);
        #pragma unroll
        for (int k = 0; k < NSTREAMS; k++)
            bulk_g2s(dst0 + k * STAGE_BYTES, src[k] + (size_t)s * STAGE_BYTES, bytes, bar);
    };

    if (tid == 0) issue(0);

    float s0 = 0.0f, s1 = 0.0f, s2 = 0.0f, s3 = 0.0f;
    uint32_t phase0 = 0, phase1 = 0;

    for (int s = 0; s < NSTAGES; s++) {
        if (tid == 0 && s + 1 < NSTAGES) issue(s + 1);

        const int b = s & 1;
        if (b == 0) { mbar_wait(bar0, phase0); phase0 ^= 1; }
        else        { mbar_wait(bar1, phase1); phase1 ^= 1; }

        const int len = (s == NSTAGES - 1) ? (CHUNK4 - (NSTAGES - 1) * STAGE4) : STAGE4;
        if (tid < len) {
            const float4* buf = reinterpret_cast<const float4*>(smem + b * BUF_BYTES);
            float4 pv = buf[4 * STAGE4 + tid];
            float4 a0 = buf[0 * STAGE4 + tid];
            float4 a1 = buf[1 * STAGE4 + tid];
            float4 a2 = buf[2 * STAGE4 + tid];
            float4 a3 = buf[3 * STAGE4 + tid];
            s0 += a0.x * pv.x + a0.y * pv.y + a0.z * pv.z + a0.w * pv.w;
            s1 += a1.x * pv.x + a1.y * pv.y + a1.z * pv.z + a1.w * pv.w;
            s2 += a2.x * pv.x + a2.y * pv.y + a2.z * pv.z + a2.w * pv.w;
            s3 += a3.x * pv.x + a3.y * pv.y + a3.z * pv.z + a3.w * pv.w;
        }
        __syncthreads();   // all consumers done with buf b before it is refilled
    }

    // Warp reduction of the 4 accumulators
    #pragma unroll
    for (int off = 16; off > 0; off >>= 1) {
        s0 += __shfl_xor_sync(0xFFFFFFFFu, s0, off);
        s1 += __shfl_xor_sync(0xFFFFFFFFu, s1, off);
        s2 += __shfl_xor_sync(0xFFFFFFFFu, s2, off);
        s3 += __shfl_xor_sync(0xFFFFFFFFu, s3, off);
    }

    const int lane = tid & 31;
    const int wid  = tid >> 5;
    if (lane == 0) { ws[0][wid] = s0; ws[1][wid] = s1; ws[2][wid] = s2; ws[3][wid] = s3; }
    __syncthreads();

    if (wid < RPB && lane < NWARPS) {
        float v = ws[wid][lane];
        #pragma unroll
        for (int off = NWARPS / 2; off > 0; off >>= 1)
            v += __shfl_xor_sync(0xFFFFu, v, off);
        if (lane == 0)
            g_partials[(mbase + wid) * SPLIT + chunk] = v;
    }

    // Fused final reduction: last block to finish sums the partials.
    __threadfence();
    if (tid == 0) {
        unsigned int t = atomicAdd(&g_ticket, 1u);
        s_last = (t == NBLOCKS - 1);
    }
    __syncthreads();

    if (s_last) {
        const int m = tid;
        if (m < NOUT) {
            float s = 0.0f;
            #pragma unroll
            for (int c = 0; c < SPLIT; c++)
                s += __ldcg(&g_partials[m * SPLIT + c]);
            out[m] = s;
        }
        if (tid == 0) g_ticket = 0;   // reset for next call
    }
}

extern "C" void kernel_launch(void* const* d_in, const int* in_sizes, int n_in,
                              void* d_out, int out_size)
{
    const float* p     = (const float*)d_in[0];   // [50000]
    const float* I     = (const float*)d_in[1];   // [784, 50000]
    const float* J     = (const float*)d_in[2];   // [784, 50000]
    const int*   inds1 = (const int*)  d_in[3];   // [100, 2]
    const int*   inds2 = (const int*)  d_in[4];   // [100, 2]
    float*       out   = (float*)d_out;           // [200]

    cudaFuncSetAttribute(gather_dot_v8,
                         cudaFuncAttributeMaxDynamicSharedMemorySize, SMEM_DYN);
    gather_dot_v8<<<NBLOCKS, NTHREADS, SMEM_DYN>>>(p, I, J, inds1, inds2, out);
}